// round 1
// baseline (speedup 1.0000x reference)
#include <cuda_runtime.h>
#include <math.h>

// Problem constants
#define BB    256
#define NN    32
#define FF    40
#define HH    100
#define MM    100
#define EFN   4
#define OUTD  128
#define NPASS 3
#define H3    300
#define KMAX  8
#define NPB   8      // nodes per block in pass kernel
#define NODES (BB*NN)

// ---------------- device scratch (no allocation allowed) ----------------
__device__ __align__(16) float g_hA[NODES*HH];
__device__ __align__(16) float g_hB[NODES*HH];
__device__ __align__(16) float g_Wt2[EFN*HH*MM];   // [f][h][m]  (m fastest -> float4 over m)
__device__ __align__(16) float g_WihT[MM*H3];      // [m][r]     (r fastest -> float4 over r)
__device__ __align__(16) float g_WhhT[HH*H3];      // [h][r]
__device__ int   g_nbr[NODES*KMAX];
__device__ int   g_typ[NODES*KMAX];
__device__ float g_wgt[NODES*KMAX];
__device__ int   g_cnt[NODES];

__device__ __forceinline__ float sigmf(float x) { return 1.0f / (1.0f + expf(-x)); }

// ---------------- prep: transpose weights ----------------
__global__ void prep_weights(const float* __restrict__ W_msg,
                             const float* __restrict__ W_ih,
                             const float* __restrict__ W_hh) {
    int gid = blockIdx.x * blockDim.x + threadIdx.x;
    const int NWT = EFN*HH*MM;            // 40000
    const int NWI = MM*H3;                // 30000
    if (gid < NWT) {
        int f = gid / (HH*MM);
        int rem = gid % (HH*MM);
        int h = rem / MM;
        int m = rem % MM;
        g_Wt2[gid] = W_msg[(m*HH + h)*EFN + f];
    } else if (gid < NWT + NWI) {
        int t = gid - NWT;
        int m = t / H3, r = t % H3;
        g_WihT[t] = W_ih[r*MM + m];
    } else if (gid < NWT + NWI + HH*H3) {
        int t = gid - NWT - NWI;
        int h = t / H3, r = t % H3;
        g_WhhT[t] = W_hh[r*HH + h];
    }
}

// ---------------- prep: compact edge lists per node ----------------
__global__ void prep_edges(const float* __restrict__ edges) {
    int p = blockIdx.x * blockDim.x + threadIdx.x;   // node index b*NN+n
    if (p >= NODES) return;
    const float4* row = (const float4*)(edges + (size_t)p * NN * EFN);
    int c = 0;
    #pragma unroll 4
    for (int g = 0; g < NN; g++) {
        float4 v = row[g];
        float vv[4] = {v.x, v.y, v.z, v.w};
        #pragma unroll
        for (int f = 0; f < EFN; f++) {
            if (vv[f] != 0.0f && c < KMAX) {
                g_nbr[p*KMAX + c] = g;
                g_typ[p*KMAX + c] = f;
                g_wgt[p*KMAX + c] = vv[f];
                c++;
            }
        }
    }
    g_cnt[p] = c;
}

// ---------------- init hidden: [nodes | 0-pad] ----------------
__global__ void init_hidden(const float* __restrict__ nodes) {
    int gid = blockIdx.x * blockDim.x + threadIdx.x;
    if (gid >= NODES*HH) return;
    int h = gid % HH;
    int p = gid / HH;
    g_hA[gid] = (h < FF) ? nodes[p*FF + h] : 0.0f;
}

// ---------------- one message pass + GRU (fused) ----------------
// grid = BB * (NN/NPB), block = 256.
__global__ __launch_bounds__(256) void pass_kernel(const float* __restrict__ hin,
                                                   float* __restrict__ hout,
                                                   const float* __restrict__ b_ih,
                                                   const float* __restrict__ b_hh) {
    __shared__ __align__(16) float sh_h[NN*HH];      // whole batch hidden (12.8KB)
    __shared__ __align__(16) float sh_msg[NPB*HH];   // 3.2KB
    __shared__ __align__(16) float sh_gi[NPB*H3];    // 9.6KB
    __shared__ __align__(16) float sh_gh[NPB*H3];    // 9.6KB

    const int b    = blockIdx.x >> 2;       // NN/NPB = 4 chunks
    const int n0   = (blockIdx.x & 3) * NPB;
    const int tid  = threadIdx.x;

    // load batch hidden
    const float4* hin4 = (const float4*)(hin + (size_t)b*NN*HH);
    float4* shh4 = (float4*)sh_h;
    for (int i = tid; i < NN*HH/4; i += 256) shh4[i] = hin4[i];
    __syncthreads();

    // ---- phase B: messages for NPB nodes ----
    // task = (local node ln, m-quad q), q in [0,25)
    for (int idx = tid; idx < NPB*25; idx += 256) {
        int ln = idx / 25;
        int q  = idx % 25;
        int p  = b*NN + n0 + ln;
        float ax = 0.f, ay = 0.f, az = 0.f, aw = 0.f;
        int c = g_cnt[p];
        for (int e = 0; e < c; e++) {
            int g = g_nbr[p*KMAX + e];
            int f = g_typ[p*KMAX + e];
            float w = g_wgt[p*KMAX + e];
            const float4* W4 = (const float4*)(g_Wt2 + f*HH*MM);
            const float* hg = sh_h + g*HH;
            #pragma unroll 4
            for (int h = 0; h < HH; h++) {
                float whv = w * hg[h];
                float4 wv = W4[h*25 + q];
                ax += whv * wv.x; ay += whv * wv.y;
                az += whv * wv.z; aw += whv * wv.w;
            }
        }
        float4* out4 = (float4*)(sh_msg + ln*HH);
        out4[q] = make_float4(ax, ay, az, aw);
    }
    __syncthreads();

    // ---- phase C1: gi = W_ih@msg + b_ih ; gh = W_hh@h + b_hh ----
    // task = (ln, r-quad q), q in [0,75)
    const float4* Wi4 = (const float4*)g_WihT;  // [m][75]
    const float4* Wh4 = (const float4*)g_WhhT;  // [h][75]
    const float4* bi4 = (const float4*)b_ih;
    const float4* bh4 = (const float4*)b_hh;
    for (int idx = tid; idx < NPB*75; idx += 256) {
        int ln = idx / 75;
        int q  = idx % 75;
        int ng = n0 + ln;
        float gx=0,gy=0,gz=0,gw=0, hx=0,hy=0,hz=0,hw=0;
        const float* msg = sh_msg + ln*HH;
        const float* hs  = sh_h + ng*HH;
        #pragma unroll 4
        for (int k = 0; k < HH; k++) {
            float x = msg[k];
            float hv = hs[k];
            float4 wi = Wi4[k*75 + q];
            float4 wh = Wh4[k*75 + q];
            gx += x*wi.x; gy += x*wi.y; gz += x*wi.z; gw += x*wi.w;
            hx += hv*wh.x; hy += hv*wh.y; hz += hv*wh.z; hw += hv*wh.w;
        }
        float4 bi = bi4[q], bh = bh4[q];
        ((float4*)(sh_gi + ln*H3))[q] = make_float4(gx+bi.x, gy+bi.y, gz+bi.z, gw+bi.w);
        ((float4*)(sh_gh + ln*H3))[q] = make_float4(hx+bh.x, hy+bh.y, hz+bh.z, hw+bh.w);
    }
    __syncthreads();

    // ---- phase C2: GRU elementwise, write hout ----
    for (int idx = tid; idx < NPB*HH; idx += 256) {
        int ln = idx / HH;
        int h  = idx % HH;
        int ng = n0 + ln;
        int p  = b*NN + ng;
        float hval = sh_h[ng*HH + h];
        float outv;
        if (g_cnt[p] == 0) {
            outv = hval;
        } else {
            float ir = sh_gi[ln*H3 + h];
            float iz = sh_gi[ln*H3 + 100 + h];
            float in = sh_gi[ln*H3 + 200 + h];
            float hr = sh_gh[ln*H3 + h];
            float hzv= sh_gh[ln*H3 + 100 + h];
            float hn = sh_gh[ln*H3 + 200 + h];
            float r = sigmf(ir + hr);
            float z = sigmf(iz + hzv);
            float n = tanhf(in + r*hn);
            outv = (1.0f - z)*n + z*hval;
        }
        hout[(size_t)p*HH + h] = outv;
    }
}

// ---------------- readout ----------------
// grid = BB, block = 256
__global__ __launch_bounds__(256) void readout_kernel(const float* __restrict__ hfin,
                                                      const float* __restrict__ nodes,
                                                      const float* __restrict__ Wg,
                                                      const float* __restrict__ bg,
                                                      const float* __restrict__ We,
                                                      const float* __restrict__ be,
                                                      const float* __restrict__ Wo,
                                                      const float* __restrict__ bo,
                                                      float* __restrict__ out) {
    __shared__ __align__(16) float sh_h[NN*HH];    // 12.8KB
    __shared__ __align__(16) float sh_x[NN*FF];    // 5.1KB
    __shared__ __align__(16) float sh_emb[NN*HH];  // 12.8KB
    __shared__ float sh_acc[HH];

    const int b = blockIdx.x;
    const int tid = threadIdx.x;

    const float4* h4 = (const float4*)(hfin + (size_t)b*NN*HH);
    float4* shh4 = (float4*)sh_h;
    for (int i = tid; i < NN*HH/4; i += 256) shh4[i] = h4[i];
    const float4* x4 = (const float4*)(nodes + (size_t)b*NN*FF);
    float4* shx4 = (float4*)sh_x;
    for (int i = tid; i < NN*FF/4; i += 256) shx4[i] = x4[i];
    __syncthreads();

    // gate + emb per (n, h)
    for (int idx = tid; idx < NN*HH; idx += 256) {
        int n = idx / HH;
        int h = idx % HH;
        float mask = (g_cnt[b*NN + n] != 0) ? 1.0f : 0.0f;
        const float* hs = sh_h + n*HH;
        const float* xs = sh_x + n*FF;
        float ga = bg[h];
        float ev = be[h];
        #pragma unroll 4
        for (int k = 0; k < HH; k++) {
            float hv = hs[k];
            ga += hv * Wg[k*HH + h];
            ev += hv * We[k*HH + h];
        }
        #pragma unroll 4
        for (int k = 0; k < FF; k++) {
            ga += xs[k] * Wg[(HH + k)*HH + h];
        }
        float gate = sigmf(ga);
        sh_emb[n*HH + h] = mask * gate * ev;
    }
    __syncthreads();

    // sum over nodes
    for (int h = tid; h < HH; h += 256) {
        float a = 0.f;
        #pragma unroll
        for (int n = 0; n < NN; n++) a += sh_emb[n*HH + h];
        sh_acc[h] = a;
    }
    __syncthreads();

    // final projection
    for (int o = tid; o < OUTD; o += 256) {
        float v = bo[o];
        #pragma unroll 4
        for (int h = 0; h < HH; h++) v += sh_acc[h] * Wo[h*OUTD + o];
        out[(size_t)b*OUTD + o] = v;
    }
}

// ---------------- launcher ----------------
extern "C" void kernel_launch(void* const* d_in, const int* in_sizes, int n_in,
                              void* d_out, int out_size) {
    const float* nodes = (const float*)d_in[0];
    const float* edges = (const float*)d_in[1];
    const float* W_msg = (const float*)d_in[2];
    const float* W_ih  = (const float*)d_in[3];
    const float* W_hh  = (const float*)d_in[4];
    const float* b_ih  = (const float*)d_in[5];
    const float* b_hh  = (const float*)d_in[6];
    const float* Wg    = (const float*)d_in[7];
    const float* bg    = (const float*)d_in[8];
    const float* We    = (const float*)d_in[9];
    const float* be    = (const float*)d_in[10];
    const float* Wo    = (const float*)d_in[11];
    const float* bo    = (const float*)d_in[12];
    float* out = (float*)d_out;

    float *hA, *hB;
    cudaGetSymbolAddress((void**)&hA, g_hA);
    cudaGetSymbolAddress((void**)&hB, g_hB);

    prep_weights<<<(100000 + 255) / 256, 256>>>(W_msg, W_ih, W_hh);
    prep_edges<<<(NODES + 255) / 256, 256>>>(edges);
    init_hidden<<<(NODES*HH + 255) / 256, 256>>>(nodes);

    // 3 passes, ping-pong A -> B -> A -> B
    pass_kernel<<<BB*(NN/NPB), 256>>>(hA, hB, b_ih, b_hh);
    pass_kernel<<<BB*(NN/NPB), 256>>>(hB, hA, b_ih, b_hh);
    pass_kernel<<<BB*(NN/NPB), 256>>>(hA, hB, b_ih, b_hh);

    readout_kernel<<<BB, 256>>>(hB, nodes, Wg, bg, We, be, Wo, bo, out);
}

// round 2
// speedup vs baseline: 2.3371x; 2.3371x over previous
#include <cuda_runtime.h>
#include <math.h>

#define BB    256
#define NN    32
#define FF    40
#define HH    100
#define MM    100
#define EFN   4
#define OUTD  128
#define H3    300
#define KMAX  8
#define NODES (BB*NN)

// ---------------- device scratch ----------------
__device__ __align__(16) float g_hA[NODES*HH];
__device__ __align__(16) float g_hB[NODES*HH];
__device__ __align__(16) float g_msg[NODES*MM];
__device__ __align__(16) float g_Wt2[EFN*HH*MM];   // [f][h][m]
__device__ __align__(16) float g_WihT[MM*H3];      // [m][r]
__device__ __align__(16) float g_WhhT[HH*H3];      // [h][r]
__device__ int   g_nbr[NODES*KMAX];
__device__ int   g_typ[NODES*KMAX];
__device__ float g_wgt[NODES*KMAX];
__device__ int   g_cnt[NODES];

__device__ __forceinline__ float sigmf(float x) { return 1.0f / (1.0f + expf(-x)); }

// ---------------- prep: transpose weights ----------------
__global__ void prep_weights(const float* __restrict__ W_msg,
                             const float* __restrict__ W_ih,
                             const float* __restrict__ W_hh) {
    int gid = blockIdx.x * blockDim.x + threadIdx.x;
    const int NWT = EFN*HH*MM;            // 40000
    const int NWI = MM*H3;                // 30000
    if (gid < NWT) {
        int f = gid / (HH*MM);
        int rem = gid % (HH*MM);
        int h = rem / MM;
        int m = rem % MM;
        g_Wt2[gid] = W_msg[(m*HH + h)*EFN + f];
    } else if (gid < NWT + NWI) {
        int t = gid - NWT;
        int m = t / H3, r = t % H3;
        g_WihT[t] = W_ih[r*MM + m];
    } else if (gid < NWT + NWI + HH*H3) {
        int t = gid - NWT - NWI;
        int h = t / H3, r = t % H3;
        g_WhhT[t] = W_hh[r*HH + h];
    }
}

// ---------------- prep: compact edge lists (warp per node) ----------------
__global__ void prep_edges(const float* __restrict__ edges) {
    int warp = (blockIdx.x * blockDim.x + threadIdx.x) >> 5;
    int lane = threadIdx.x & 31;
    if (warp >= NODES) return;
    int p = warp;
    // lane = neighbor index g (NN == 32)
    float4 v = ((const float4*)edges)[(size_t)p * NN + lane];
    float vv[4] = {v.x, v.y, v.z, v.w};
    int nl = (vv[0]!=0.f) + (vv[1]!=0.f) + (vv[2]!=0.f) + (vv[3]!=0.f);
    // inclusive scan over lanes
    int inc = nl;
    #pragma unroll
    for (int off = 1; off < 32; off <<= 1) {
        int t = __shfl_up_sync(0xFFFFFFFFu, inc, off);
        if (lane >= off) inc += t;
    }
    int excl = inc - nl;
    int total = __shfl_sync(0xFFFFFFFFu, inc, 31);
    int c = excl;
    #pragma unroll
    for (int f = 0; f < EFN; f++) {
        if (vv[f] != 0.f && c < KMAX) {
            g_nbr[p*KMAX + c] = lane;
            g_typ[p*KMAX + c] = f;
            g_wgt[p*KMAX + c] = vv[f];
            c++;
        }
    }
    if (lane == 0) g_cnt[p] = (total < KMAX) ? total : KMAX;
}

// ---------------- init hidden ----------------
__global__ void init_hidden(const float* __restrict__ nodes) {
    int gid = blockIdx.x * blockDim.x + threadIdx.x;
    if (gid >= NODES*HH) return;
    int h = gid % HH;
    int p = gid / HH;
    g_hA[gid] = (h < FF) ? nodes[p*FF + h] : 0.0f;
}

// ---------------- messages: per-batch dense transform + gather ----------------
// grid = BB, block = 512. Computes g_msg[p][m] for all nodes of batch b.
__global__ __launch_bounds__(512) void msg_kernel(const float* __restrict__ hin) {
    __shared__ __align__(16) float sh_hT[HH][NN];        // 12.8KB, [h][n]
    __shared__ __align__(16) float sh_T2[EFN*NN*MM];     // 51.2KB, [f][g][m]

    const int b   = blockIdx.x;
    const int tid = threadIdx.x;
    const int p0  = b * NN;

    // transposed load of batch hidden (contiguous smem writes, gathered LDG)
    for (int idx = tid; idx < NN*HH; idx += 512) {
        int n = idx & 31;        // idx % 32
        int h = idx >> 5;        // idx / 32
        sh_hT[h][n] = hin[(size_t)(p0 + n)*HH + h];
    }
    __syncthreads();

    // T[f][g][m] = sum_h W_f[h][m] * h_g[h]  -- 32-node register tile
    if (tid < EFN*MM) {
        const int f = tid / MM;
        const int m = tid % MM;
        float acc[NN];
        #pragma unroll
        for (int n = 0; n < NN; n++) acc[n] = 0.f;
        const float* Wf = g_Wt2 + f*HH*MM + m;
        for (int h = 0; h < HH; h++) {
            float w = Wf[h*MM];
            const float4* hp = (const float4*)&sh_hT[h][0];
            #pragma unroll
            for (int j = 0; j < 8; j++) {
                float4 v = hp[j];
                acc[4*j+0] += w*v.x; acc[4*j+1] += w*v.y;
                acc[4*j+2] += w*v.z; acc[4*j+3] += w*v.w;
            }
        }
        float* Trow = sh_T2 + (f*NN)*MM + m;
        #pragma unroll
        for (int n = 0; n < NN; n++) Trow[n*MM] = acc[n];
    }
    __syncthreads();

    // gather: msg[n][m] = sum_e w_e * T[f_e][g_e][m]
    for (int idx = tid; idx < NN*25; idx += 512) {
        int n = idx / 25;
        int q = idx % 25;
        int p = p0 + n;
        float4 a = make_float4(0.f, 0.f, 0.f, 0.f);
        int c = g_cnt[p];
        for (int e = 0; e < c; e++) {
            int g = g_nbr[p*KMAX + e];
            int f = g_typ[p*KMAX + e];
            float w = g_wgt[p*KMAX + e];
            float4 v = ((const float4*)(sh_T2 + (f*NN + g)*MM))[q];
            a.x += w*v.x; a.y += w*v.y; a.z += w*v.z; a.w += w*v.w;
        }
        ((float4*)(g_msg + (size_t)p*MM))[q] = a;
    }
}

// ---------------- GRU: gi/gh GEMMs + elementwise ----------------
// grid = BB*2 (16 nodes per block), block = 320.
__global__ __launch_bounds__(320) void gru_kernel(const float* __restrict__ hin,
                                                  float* __restrict__ hout,
                                                  const float* __restrict__ b_ih,
                                                  const float* __restrict__ b_hh) {
    __shared__ __align__(16) float sh_hT[HH][16];   // 6.4KB
    __shared__ __align__(16) float sh_mT[HH][16];   // 6.4KB
    __shared__ __align__(16) float sh_gi[16][H3];   // 19.2KB
    __shared__ __align__(16) float sh_gh[16][H3];   // 19.2KB

    const int tid = threadIdx.x;
    const int p0  = blockIdx.x * 16;

    for (int idx = tid; idx < 16*HH; idx += 320) {
        int n = idx & 15;
        int h = idx >> 4;
        sh_hT[h][n] = hin[(size_t)(p0 + n)*HH + h];
        sh_mT[h][n] = g_msg[(size_t)(p0 + n)*HH + h];
    }
    __syncthreads();

    if (tid < H3) {
        const int r = tid;
        float gi[16], gh[16];
        #pragma unroll
        for (int n = 0; n < 16; n++) { gi[n] = 0.f; gh[n] = 0.f; }
        for (int k = 0; k < HH; k++) {
            float wi = g_WihT[k*H3 + r];
            float wh = g_WhhT[k*H3 + r];
            const float4* mp = (const float4*)&sh_mT[k][0];
            const float4* hp = (const float4*)&sh_hT[k][0];
            #pragma unroll
            for (int j = 0; j < 4; j++) {
                float4 mv = mp[j];
                float4 hv = hp[j];
                gi[4*j+0] += wi*mv.x; gi[4*j+1] += wi*mv.y;
                gi[4*j+2] += wi*mv.z; gi[4*j+3] += wi*mv.w;
                gh[4*j+0] += wh*hv.x; gh[4*j+1] += wh*hv.y;
                gh[4*j+2] += wh*hv.z; gh[4*j+3] += wh*hv.w;
            }
        }
        float bi = b_ih[r];
        float bh = b_hh[r];
        #pragma unroll
        for (int n = 0; n < 16; n++) {
            sh_gi[n][r] = gi[n] + bi;
            sh_gh[n][r] = gh[n] + bh;
        }
    }
    __syncthreads();

    for (int idx = tid; idx < 16*HH; idx += 320) {
        int n = idx / HH;
        int h = idx % HH;
        int p = p0 + n;
        float hval = sh_hT[h][n];
        float outv;
        if (g_cnt[p] == 0) {
            outv = hval;
        } else {
            float r = sigmf(sh_gi[n][h]       + sh_gh[n][h]);
            float z = sigmf(sh_gi[n][100 + h] + sh_gh[n][100 + h]);
            float nn = tanhf(sh_gi[n][200 + h] + r * sh_gh[n][200 + h]);
            outv = (1.0f - z)*nn + z*hval;
        }
        hout[(size_t)p*HH + h] = outv;
    }
}

// ---------------- readout ----------------
// grid = BB, block = 256
__global__ __launch_bounds__(256) void readout_kernel(const float* __restrict__ hfin,
                                                      const float* __restrict__ nodes,
                                                      const float* __restrict__ Wg,
                                                      const float* __restrict__ bg,
                                                      const float* __restrict__ We,
                                                      const float* __restrict__ be,
                                                      const float* __restrict__ Wo,
                                                      const float* __restrict__ bo,
                                                      float* __restrict__ out) {
    __shared__ __align__(16) float sh_hT[HH][NN];   // 12.8KB
    __shared__ __align__(16) float sh_xT[FF][NN];   // 5.1KB
    __shared__ float sh_part[2][HH];
    __shared__ float sh_acc[HH];

    const int b = blockIdx.x;
    const int tid = threadIdx.x;
    const int p0 = b * NN;

    for (int idx = tid; idx < NN*HH; idx += 256) {
        int n = idx & 31;
        int h = idx >> 5;
        sh_hT[h][n] = hfin[(size_t)(p0 + n)*HH + h];
    }
    for (int idx = tid; idx < NN*FF; idx += 256) {
        int n = idx & 31;
        int k = idx >> 5;
        sh_xT[k][n] = nodes[(size_t)(p0 + n)*FF + k];
    }
    __syncthreads();

    if (tid < 200) {
        const int h   = tid % HH;
        const int grp = tid / HH;
        const int n0  = grp * 16;
        float ga[16], ev[16];
        #pragma unroll
        for (int n = 0; n < 16; n++) { ga[n] = 0.f; ev[n] = 0.f; }
        for (int k = 0; k < HH; k++) {
            float wg = Wg[k*HH + h];
            float we = We[k*HH + h];
            const float4* hp = (const float4*)&sh_hT[k][n0];
            #pragma unroll
            for (int j = 0; j < 4; j++) {
                float4 v = hp[j];
                ga[4*j+0] += wg*v.x; ga[4*j+1] += wg*v.y;
                ga[4*j+2] += wg*v.z; ga[4*j+3] += wg*v.w;
                ev[4*j+0] += we*v.x; ev[4*j+1] += we*v.y;
                ev[4*j+2] += we*v.z; ev[4*j+3] += we*v.w;
            }
        }
        for (int k = 0; k < FF; k++) {
            float wg = Wg[(HH + k)*HH + h];
            const float4* xp = (const float4*)&sh_xT[k][n0];
            #pragma unroll
            for (int j = 0; j < 4; j++) {
                float4 v = xp[j];
                ga[4*j+0] += wg*v.x; ga[4*j+1] += wg*v.y;
                ga[4*j+2] += wg*v.z; ga[4*j+3] += wg*v.w;
            }
        }
        float bgv = bg[h];
        float bev = be[h];
        float s = 0.f;
        #pragma unroll
        for (int n = 0; n < 16; n++) {
            if (g_cnt[p0 + n0 + n] != 0) {
                s += sigmf(ga[n] + bgv) * (ev[n] + bev);
            }
        }
        sh_part[grp][h] = s;
    }
    __syncthreads();
    if (tid < HH) sh_acc[tid] = sh_part[0][tid] + sh_part[1][tid];
    __syncthreads();

    for (int o = tid; o < OUTD; o += 256) {
        float v = bo[o];
        #pragma unroll 4
        for (int k = 0; k < HH; k++) v += sh_acc[k] * Wo[k*OUTD + o];
        out[(size_t)b*OUTD + o] = v;
    }
}

// ---------------- launcher ----------------
extern "C" void kernel_launch(void* const* d_in, const int* in_sizes, int n_in,
                              void* d_out, int out_size) {
    const float* nodes = (const float*)d_in[0];
    const float* edges = (const float*)d_in[1];
    const float* W_msg = (const float*)d_in[2];
    const float* W_ih  = (const float*)d_in[3];
    const float* W_hh  = (const float*)d_in[4];
    const float* b_ih  = (const float*)d_in[5];
    const float* b_hh  = (const float*)d_in[6];
    const float* Wg    = (const float*)d_in[7];
    const float* bg    = (const float*)d_in[8];
    const float* We    = (const float*)d_in[9];
    const float* be    = (const float*)d_in[10];
    const float* Wo    = (const float*)d_in[11];
    const float* bo    = (const float*)d_in[12];
    float* out = (float*)d_out;

    float *hA, *hB;
    cudaGetSymbolAddress((void**)&hA, g_hA);
    cudaGetSymbolAddress((void**)&hB, g_hB);

    prep_weights<<<(100000 + 255) / 256, 256>>>(W_msg, W_ih, W_hh);
    prep_edges<<<(NODES*32 + 255) / 256, 256>>>(edges);
    init_hidden<<<(NODES*HH + 255) / 256, 256>>>(nodes);

    // pass 1
    msg_kernel<<<BB, 512>>>(hA);
    gru_kernel<<<BB*2, 320>>>(hA, hB, b_ih, b_hh);
    // pass 2
    msg_kernel<<<BB, 512>>>(hB);
    gru_kernel<<<BB*2, 320>>>(hB, hA, b_ih, b_hh);
    // pass 3
    msg_kernel<<<BB, 512>>>(hA);
    gru_kernel<<<BB*2, 320>>>(hA, hB, b_ih, b_hh);

    readout_kernel<<<BB, 256>>>(hB, nodes, Wg, bg, We, be, Wo, bo, out);
}